// round 5
// baseline (speedup 1.0000x reference)
#include <cuda_runtime.h>
#include <cuda_bf16.h>
#include <float.h>
#include <cstdint>

// Problem shape (fixed per reference)
#define BATCH 32
#define SEQ   4096
#define HID   1024
#define TOP   512
#define CATK  (2*HID + TOP)   // 2560

#define NSPLIT 16                        // S-splits per batch in attention pass
#define ROWS_PER_SPLIT (SEQ / NSPLIT)    // 256 rows per CTA
#define WARPS 8
#define ROWS_PER_WARP (ROWS_PER_SPLIT / WARPS)  // 32 rows per warp
#define VPL 8                            // float4 per lane per row (1024/4/32)
#define ATTN_SMEM (WARPS * 2 * 256 * 16) // 64 KB: per-warp double row buffer

#define KSPL_MAX 5                       // max K-splits across both GEMMs

// ---------------- scratch (__device__ globals; no allocations) --------------
__device__ float g_gamma [BATCH * HID];
__device__ float g_scores[BATCH * SEQ];
__device__ float g_cpart [BATCH * NSPLIT * HID];
__device__ float g_mzpart[BATCH * NSPLIT * 2];
__device__ float g_cat   [BATCH * CATK];
__device__ float g_part  [KSPL_MAX * BATCH * HID];   // GEMM K-split partials

// ---------------------------------------------------------------------------
// Kernel 1a: K-split GEMM partial.  part[kblk][b][h] = sum_{k in slice} in[b][k]*W[h][k]
// grid = (Hout/16, KSPL), block = 256. Each warp owns 2 h rows; 16 h per CTA.
// Kslice must be a multiple of 256.
// ---------------------------------------------------------------------------
__global__ void __launch_bounds__(256)
gemm_part_kernel(const float* __restrict__ in, const float* __restrict__ W,
                 int K, int Kslice, int Hout)
{
    __shared__ float4 tile[BATCH * 64];   // 32 b x 256 k  (32 KB)
    const int t    = threadIdx.x;
    const int warp = t >> 5;
    const int lane = t & 31;
    const int h0   = blockIdx.x * 16 + warp * 2;
    const int h1   = h0 + 1;
    const int kbeg = blockIdx.y * Kslice;

    float acc0[BATCH], acc1[BATCH];
    #pragma unroll
    for (int b = 0; b < BATCH; ++b) { acc0[b] = 0.f; acc1[b] = 0.f; }

    for (int k0 = kbeg; k0 < kbeg + Kslice; k0 += 256) {
        #pragma unroll
        for (int i = 0; i < 8; ++i) {
            int idx = t + i * 256;
            int bb  = idx >> 6;
            int kk  = idx & 63;
            tile[idx] = ((const float4*)(in + (size_t)bb * K + k0))[kk];
        }
        __syncthreads();

        #pragma unroll
        for (int c = 0; c < 2; ++c) {
            float4 wa = ((const float4*)(W + (size_t)h0 * K + k0 + c * 128))[lane];
            float4 wb = ((const float4*)(W + (size_t)h1 * K + k0 + c * 128))[lane];
            #pragma unroll
            for (int bb = 0; bb < BATCH; ++bb) {
                float4 xv = tile[bb * 64 + c * 32 + lane];
                acc0[bb] += wa.x * xv.x + wa.y * xv.y + wa.z * xv.z + wa.w * xv.w;
                acc1[bb] += wb.x * xv.x + wb.y * xv.y + wb.z * xv.z + wb.w * xv.w;
            }
        }
        __syncthreads();
    }

    #pragma unroll
    for (int off = 16; off; off >>= 1)
        #pragma unroll
        for (int bb = 0; bb < BATCH; ++bb) {
            acc0[bb] += __shfl_xor_sync(0xFFFFFFFFu, acc0[bb], off);
            acc1[bb] += __shfl_xor_sync(0xFFFFFFFFu, acc1[bb], off);
        }

    // lane <-> batch
    g_part[((size_t)blockIdx.y * BATCH + lane) * Hout + h0] = acc0[lane];
    g_part[((size_t)blockIdx.y * BATCH + lane) * Hout + h1] = acc1[lane];
}

// ---------------------------------------------------------------------------
// Kernel 1b: sum K-split partials + bias (+tanh).  out[b][h], float4 over h.
// grid = BATCH*Hout/4/256, block = 256.
// ---------------------------------------------------------------------------
__global__ void __launch_bounds__(256)
gemm_reduce_kernel(const float* __restrict__ bias, float* __restrict__ out,
                   int Hout, int kspl, int act)
{
    const int i  = blockIdx.x * 256 + threadIdx.x;   // float4 index
    const int hq = Hout >> 2;
    const int b  = i / hq;
    const int h4 = i - b * hq;

    float4 s = ((const float4*)bias)[h4];
    for (int p = 0; p < kspl; ++p) {
        float4 v = ((const float4*)(g_part + ((size_t)p * BATCH + b) * Hout))[h4];
        s.x += v.x; s.y += v.y; s.z += v.z; s.w += v.w;
    }
    if (act) {
        s.x = tanhf(s.x); s.y = tanhf(s.y);
        s.z = tanhf(s.z); s.w = tanhf(s.w);
    }
    ((float4*)(out + (size_t)b * Hout))[h4] = s;
}

// ---------------------------------------------------------------------------
// Kernel 2: warp-autonomous fused scores + online softmax + weighted sum,
// with cp.async double-buffered row staging. grid = (NSPLIT, BATCH), block=256.
// ---------------------------------------------------------------------------
__device__ __forceinline__ void stage_row(uint32_t dst_base, const float4* src)
{
    #pragma unroll
    for (int i = 0; i < VPL; ++i)
        asm volatile("cp.async.cg.shared.global [%0], [%1], 16;\n"
                     :: "r"(dst_base + i * 512), "l"(src + i * 32));
}

__global__ void __launch_bounds__(256, 2)
attn_pass_kernel(const float* __restrict__ ctx)
{
    extern __shared__ float4 sbuf[];          // [WARPS][2][256] float4
    __shared__ float s_m[WARPS], s_Z[WARPS];

    const int t     = threadIdx.x;
    const int warp  = t >> 5;
    const int lane  = t & 31;
    const int split = blockIdx.x;
    const int b     = blockIdx.y;

    float4 g[VPL];
    {
        const float4* gp = (const float4*)(g_gamma + (size_t)b * HID);
        #pragma unroll
        for (int i = 0; i < VPL; ++i) g[i] = gp[lane + 32 * i];
    }

    const int row0 = split * ROWS_PER_SPLIT + warp * ROWS_PER_WARP;
    const float4* base = (const float4*)(ctx + ((size_t)b * SEQ + row0) * HID);

    float4* wbuf = sbuf + warp * 2 * 256;
    const uint32_t wbuf_addr =
        (uint32_t)__cvta_generic_to_shared(wbuf) + (uint32_t)lane * 16;

    #pragma unroll
    for (int pre = 0; pre < 2; ++pre) {
        stage_row(wbuf_addr + pre * 4096, base + pre * 256 + lane);
        asm volatile("cp.async.commit_group;\n");
    }

    float  m = -FLT_MAX, Z = 0.f;
    float4 c[VPL];
    #pragma unroll
    for (int i = 0; i < VPL; ++i) c[i] = make_float4(0.f, 0.f, 0.f, 0.f);

    for (int r = 0; r < ROWS_PER_WARP; ++r) {
        asm volatile("cp.async.wait_group 1;\n");
        __syncwarp();

        const float4* vbuf = wbuf + (r & 1) * 256;
        float4 v[VPL];
        #pragma unroll
        for (int i = 0; i < VPL; ++i) v[i] = vbuf[lane + 32 * i];
        __syncwarp();

        if (r + 2 < ROWS_PER_WARP)
            stage_row(wbuf_addr + (r & 1) * 4096, base + (r + 2) * 256 + lane);
        asm volatile("cp.async.commit_group;\n");

        float p = 0.f;
        #pragma unroll
        for (int i = 0; i < VPL; ++i)
            p += v[i].x * g[i].x + v[i].y * g[i].y + v[i].z * g[i].z + v[i].w * g[i].w;

        #pragma unroll
        for (int off = 16; off; off >>= 1)
            p += __shfl_xor_sync(0xFFFFFFFFu, p, off);

        if (lane == 0) g_scores[(size_t)b * SEQ + row0 + r] = p;

        if (p > m) {
            const float scale = __expf(m - p);
            Z *= scale;
            #pragma unroll
            for (int i = 0; i < VPL; ++i) {
                c[i].x *= scale; c[i].y *= scale;
                c[i].z *= scale; c[i].w *= scale;
            }
            m = p;
        }
        const float e = __expf(p - m);
        Z += e;
        #pragma unroll
        for (int i = 0; i < VPL; ++i) {
            c[i].x += e * v[i].x;  c[i].y += e * v[i].y;
            c[i].z += e * v[i].z;  c[i].w += e * v[i].w;
        }
    }

    asm volatile("cp.async.wait_group 0;\n");
    __syncthreads();
    float* s_c = (float*)sbuf;
    #pragma unroll
    for (int i = 0; i < VPL; ++i)
        ((float4*)(s_c + warp * HID))[lane + 32 * i] = c[i];
    if (lane == 0) { s_m[warp] = m; s_Z[warp] = Z; }
    __syncthreads();

    float mg = s_m[0];
    #pragma unroll
    for (int w = 1; w < WARPS; ++w) mg = fmaxf(mg, s_m[w]);

    float wsc[WARPS], Zg = 0.f;
    #pragma unroll
    for (int w = 0; w < WARPS; ++w) {
        wsc[w] = __expf(s_m[w] - mg);
        Zg += s_Z[w] * wsc[w];
    }

    float4 acc = make_float4(0.f, 0.f, 0.f, 0.f);
    #pragma unroll
    for (int w = 0; w < WARPS; ++w) {
        float4 cw = ((const float4*)(s_c + w * HID))[t];
        acc.x += wsc[w] * cw.x;  acc.y += wsc[w] * cw.y;
        acc.z += wsc[w] * cw.z;  acc.w += wsc[w] * cw.w;
    }
    ((float4*)(g_cpart + ((size_t)b * NSPLIT + split) * HID))[t] = acc;
    if (t == 0) {
        g_mzpart[(b * NSPLIT + split) * 2 + 0] = mg;
        g_mzpart[(b * NSPLIT + split) * 2 + 1] = Zg;
    }
}

// ---------------------------------------------------------------------------
// Kernel 3: cross-split reduction -> c_t, builds cat buffer, writes weights.
// grid = BATCH, block = 256.
// ---------------------------------------------------------------------------
__global__ void __launch_bounds__(256)
reduce_c_kernel(const float* __restrict__ x, const float* __restrict__ topic,
                float* __restrict__ out_w)
{
    const int b = blockIdx.x;
    const int t = threadIdx.x;

    float mg = -FLT_MAX;
    #pragma unroll
    for (int i = 0; i < NSPLIT; ++i)
        mg = fmaxf(mg, g_mzpart[(b * NSPLIT + i) * 2 + 0]);

    float Zg = 0.f;
    float wsc[NSPLIT];
    #pragma unroll
    for (int i = 0; i < NSPLIT; ++i) {
        float mi = g_mzpart[(b * NSPLIT + i) * 2 + 0];
        float zi = g_mzpart[(b * NSPLIT + i) * 2 + 1];
        wsc[i] = __expf(mi - mg);
        Zg += zi * wsc[i];
    }
    const float inv = 1.f / Zg;

    float4 c = make_float4(0.f, 0.f, 0.f, 0.f);
    #pragma unroll
    for (int i = 0; i < NSPLIT; ++i) {
        float4 cp = ((const float4*)(g_cpart + ((size_t)b * NSPLIT + i) * HID))[t];
        c.x += wsc[i] * cp.x;  c.y += wsc[i] * cp.y;
        c.z += wsc[i] * cp.z;  c.w += wsc[i] * cp.w;
    }
    c.x *= inv; c.y *= inv; c.z *= inv; c.w *= inv;

    ((float4*)(g_cat + (size_t)b * CATK))[t] = c;
    ((float4*)(g_cat + (size_t)b * CATK + HID))[t] =
        ((const float4*)(x + (size_t)b * HID))[t];
    if (t < TOP / 4)
        ((float4*)(g_cat + (size_t)b * CATK + 2 * HID))[t] =
            ((const float4*)(topic + (size_t)b * TOP))[t];

    const float4* sc = (const float4*)(g_scores + (size_t)b * SEQ);
    float4*       ow = (float4*)(out_w + (size_t)b * SEQ);
    #pragma unroll
    for (int i = 0; i < SEQ / 4 / 256; ++i) {
        float4 s = sc[t + i * 256];
        float4 w;
        w.x = __expf(s.x - mg) * inv;
        w.y = __expf(s.y - mg) * inv;
        w.z = __expf(s.z - mg) * inv;
        w.w = __expf(s.w - mg) * inv;
        ow[t + i * 256] = w;
    }
}

// ---------------------------------------------------------------------------
extern "C" void kernel_launch(void* const* d_in, const int* in_sizes, int n_in,
                              void* d_out, int out_size)
{
    const float* x     = (const float*)d_in[0];
    const float* ctx   = (const float*)d_in[1];
    const float* topic = (const float*)d_in[2];
    const float* W_in  = (const float*)d_in[3];
    const float* b_in  = (const float*)d_in[4];
    const float* W_out = (const float*)d_in[5];
    const float* b_out = (const float*)d_in[6];

    float* out  = (float*)d_out;                 // [BATCH,HID] output
    float* outw = out + BATCH * HID;             // [BATCH,SEQ] weights

    float* gamma_ptr;
    cudaGetSymbolAddress((void**)&gamma_ptr, g_gamma);
    float* cat_ptr;
    cudaGetSymbolAddress((void**)&cat_ptr, g_cat);

    static int smem_set = 0;
    if (!smem_set) {
        cudaFuncSetAttribute(attn_pass_kernel,
                             cudaFuncAttributeMaxDynamicSharedMemorySize,
                             ATTN_SMEM);
        smem_set = 1;
    }

    // 1) gamma = x @ W_in^T + b_in   (K=1024, 4 splits of 256)
    gemm_part_kernel<<<dim3(HID / 16, 4), 256>>>(x, W_in, HID, 256, HID);
    gemm_reduce_kernel<<<BATCH * HID / 4 / 256, 256>>>(b_in, gamma_ptr, HID, 4, 0);

    // 2) fused scores + online softmax + partial c_t (single context pass)
    attn_pass_kernel<<<dim3(NSPLIT, BATCH), 256, ATTN_SMEM>>>(ctx);

    // 3) cross-split reduce + build cat + final weights
    reduce_c_kernel<<<BATCH, 256>>>(x, topic, outw);

    // 4) output = tanh(cat @ W_out^T + b_out)   (K=2560, 5 splits of 512)
    gemm_part_kernel<<<dim3(HID / 16, 5), 256>>>(cat_ptr, W_out, CATK, 512, HID);
    gemm_reduce_kernel<<<BATCH * HID / 4 / 256, 256>>>(b_out, out, HID, 5, 1);
}

// round 6
// speedup vs baseline: 1.6984x; 1.6984x over previous
#include <cuda_runtime.h>
#include <cuda_bf16.h>
#include <float.h>
#include <cstdint>

// Problem shape (fixed per reference)
#define BATCH 32
#define SEQ   4096
#define HID   1024
#define TOP   512
#define CATK  (2*HID + TOP)   // 2560

#define NSPLIT 16                        // S-splits per batch in attention pass
#define ROWS_PER_SPLIT (SEQ / NSPLIT)    // 256 rows per CTA
#define WARPS 8
#define ROWS_PER_WARP (ROWS_PER_SPLIT / WARPS)  // 32 rows per warp
#define VPL 8                            // float4 per lane per row (1024/4/32)
#define ATTN_SMEM (WARPS * 2 * 256 * 16) // 64 KB: per-warp double row buffer

#define GEMM_BH 16                       // batches per GEMM CTA (2 halves)

// ---------------- scratch (__device__ globals; no allocations) --------------
__device__ float g_gamma [BATCH * HID];
__device__ float g_scores[BATCH * SEQ];
__device__ float g_cpart [BATCH * NSPLIT * HID];
__device__ float g_mzpart[BATCH * NSPLIT * 2];
__device__ float g_cat   [BATCH * CATK];

// ---------------------------------------------------------------------------
// Kernel 1: small GEMM  out[b][h] = act( bias[h] + sum_k in[b][k]*W[h][k] )
// grid = (Hout/16, 2), block = 256. Each warp owns 2 h rows; each CTA one
// 16-batch half. Each smem x-read feeds 8 FFMA (2 h x float4).
// K must be a multiple of 256.
// ---------------------------------------------------------------------------
__global__ void __launch_bounds__(256)
small_gemm_kernel(const float* __restrict__ in, const float* __restrict__ W,
                  const float* __restrict__ bias, float* __restrict__ out,
                  int K, int Hout, int act)
{
    __shared__ float4 tile[GEMM_BH * 64];   // 16 b x 256 k  (16 KB)
    const int t    = threadIdx.x;
    const int warp = t >> 5;
    const int lane = t & 31;
    const int h0   = blockIdx.x * 16 + warp * 2;
    const int h1   = h0 + 1;
    const int b0   = blockIdx.y * GEMM_BH;

    float acc0[GEMM_BH], acc1[GEMM_BH];
    #pragma unroll
    for (int b = 0; b < GEMM_BH; ++b) { acc0[b] = 0.f; acc1[b] = 0.f; }

    for (int k0 = 0; k0 < K; k0 += 256) {
        #pragma unroll
        for (int i = 0; i < 4; ++i) {
            int idx = t + i * 256;          // 1024 float4 total
            int bb  = idx >> 6;
            int kk  = idx & 63;
            tile[idx] = ((const float4*)(in + (size_t)(b0 + bb) * K + k0))[kk];
        }
        __syncthreads();

        #pragma unroll
        for (int c = 0; c < 2; ++c) {
            float4 wa = ((const float4*)(W + (size_t)h0 * K + k0 + c * 128))[lane];
            float4 wb = ((const float4*)(W + (size_t)h1 * K + k0 + c * 128))[lane];
            #pragma unroll
            for (int bb = 0; bb < GEMM_BH; ++bb) {
                float4 xv = tile[bb * 64 + c * 32 + lane];
                acc0[bb] += wa.x * xv.x + wa.y * xv.y + wa.z * xv.z + wa.w * xv.w;
                acc1[bb] += wb.x * xv.x + wb.y * xv.y + wb.z * xv.z + wb.w * xv.w;
            }
        }
        __syncthreads();
    }

    #pragma unroll
    for (int off = 16; off; off >>= 1)
        #pragma unroll
        for (int bb = 0; bb < GEMM_BH; ++bb) {
            acc0[bb] += __shfl_xor_sync(0xFFFFFFFFu, acc0[bb], off);
            acc1[bb] += __shfl_xor_sync(0xFFFFFFFFu, acc1[bb], off);
        }

    // epilogue: lanes 0-15 write h0 (batch = lane), lanes 16-31 write h1
    const int bl = lane & 15;
    float v = (lane < 16) ? acc0[bl] : acc1[bl];
    const int h = (lane < 16) ? h0 : h1;
    v += bias[h];
    if (act) v = tanhf(v);
    out[(size_t)(b0 + bl) * Hout + h] = v;
}

// ---------------------------------------------------------------------------
// Kernel 2: warp-autonomous fused scores + online softmax + weighted sum,
// with cp.async double-buffered row staging. grid = (NSPLIT, BATCH), block=256.
// ---------------------------------------------------------------------------
__device__ __forceinline__ void stage_row(uint32_t dst_base, const float4* src)
{
    #pragma unroll
    for (int i = 0; i < VPL; ++i)
        asm volatile("cp.async.cg.shared.global [%0], [%1], 16;\n"
                     :: "r"(dst_base + i * 512), "l"(src + i * 32));
}

__global__ void __launch_bounds__(256, 2)
attn_pass_kernel(const float* __restrict__ ctx)
{
    extern __shared__ float4 sbuf[];          // [WARPS][2][256] float4
    __shared__ float s_m[WARPS], s_Z[WARPS];

    const int t     = threadIdx.x;
    const int warp  = t >> 5;
    const int lane  = t & 31;
    const int split = blockIdx.x;
    const int b     = blockIdx.y;

    float4 g[VPL];
    {
        const float4* gp = (const float4*)(g_gamma + (size_t)b * HID);
        #pragma unroll
        for (int i = 0; i < VPL; ++i) g[i] = gp[lane + 32 * i];
    }

    const int row0 = split * ROWS_PER_SPLIT + warp * ROWS_PER_WARP;
    const float4* base = (const float4*)(ctx + ((size_t)b * SEQ + row0) * HID);

    float4* wbuf = sbuf + warp * 2 * 256;
    const uint32_t wbuf_addr =
        (uint32_t)__cvta_generic_to_shared(wbuf) + (uint32_t)lane * 16;

    #pragma unroll
    for (int pre = 0; pre < 2; ++pre) {
        stage_row(wbuf_addr + pre * 4096, base + pre * 256 + lane);
        asm volatile("cp.async.commit_group;\n");
    }

    float  m = -FLT_MAX, Z = 0.f;
    float4 c[VPL];
    #pragma unroll
    for (int i = 0; i < VPL; ++i) c[i] = make_float4(0.f, 0.f, 0.f, 0.f);

    for (int r = 0; r < ROWS_PER_WARP; ++r) {
        asm volatile("cp.async.wait_group 1;\n");
        __syncwarp();

        const float4* vbuf = wbuf + (r & 1) * 256;
        float4 v[VPL];
        #pragma unroll
        for (int i = 0; i < VPL; ++i) v[i] = vbuf[lane + 32 * i];
        __syncwarp();

        if (r + 2 < ROWS_PER_WARP)
            stage_row(wbuf_addr + (r & 1) * 4096, base + (r + 2) * 256 + lane);
        asm volatile("cp.async.commit_group;\n");

        float p = 0.f;
        #pragma unroll
        for (int i = 0; i < VPL; ++i)
            p += v[i].x * g[i].x + v[i].y * g[i].y + v[i].z * g[i].z + v[i].w * g[i].w;

        #pragma unroll
        for (int off = 16; off; off >>= 1)
            p += __shfl_xor_sync(0xFFFFFFFFu, p, off);

        if (lane == 0) g_scores[(size_t)b * SEQ + row0 + r] = p;

        if (p > m) {
            const float scale = __expf(m - p);
            Z *= scale;
            #pragma unroll
            for (int i = 0; i < VPL; ++i) {
                c[i].x *= scale; c[i].y *= scale;
                c[i].z *= scale; c[i].w *= scale;
            }
            m = p;
        }
        const float e = __expf(p - m);
        Z += e;
        #pragma unroll
        for (int i = 0; i < VPL; ++i) {
            c[i].x += e * v[i].x;  c[i].y += e * v[i].y;
            c[i].z += e * v[i].z;  c[i].w += e * v[i].w;
        }
    }

    asm volatile("cp.async.wait_group 0;\n");
    __syncthreads();
    float* s_c = (float*)sbuf;
    #pragma unroll
    for (int i = 0; i < VPL; ++i)
        ((float4*)(s_c + warp * HID))[lane + 32 * i] = c[i];
    if (lane == 0) { s_m[warp] = m; s_Z[warp] = Z; }
    __syncthreads();

    float mg = s_m[0];
    #pragma unroll
    for (int w = 1; w < WARPS; ++w) mg = fmaxf(mg, s_m[w]);

    float wsc[WARPS], Zg = 0.f;
    #pragma unroll
    for (int w = 0; w < WARPS; ++w) {
        wsc[w] = __expf(s_m[w] - mg);
        Zg += s_Z[w] * wsc[w];
    }

    float4 acc = make_float4(0.f, 0.f, 0.f, 0.f);
    #pragma unroll
    for (int w = 0; w < WARPS; ++w) {
        float4 cw = ((const float4*)(s_c + w * HID))[t];
        acc.x += wsc[w] * cw.x;  acc.y += wsc[w] * cw.y;
        acc.z += wsc[w] * cw.z;  acc.w += wsc[w] * cw.w;
    }
    ((float4*)(g_cpart + ((size_t)b * NSPLIT + split) * HID))[t] = acc;
    if (t == 0) {
        g_mzpart[(b * NSPLIT + split) * 2 + 0] = mg;
        g_mzpart[(b * NSPLIT + split) * 2 + 1] = Zg;
    }
}

// ---------------------------------------------------------------------------
// Kernel 3: cross-split reduce + cat build + weights, parallelized.
// grid = (BATCH, 5): y=0 -> c_t/cat; y=1..4 -> quarter of the weights row.
// All CTAs recompute mg/Zg from the tiny g_mzpart array (32 loads).
// ---------------------------------------------------------------------------
__global__ void __launch_bounds__(256)
reduce_c_kernel(const float* __restrict__ x, const float* __restrict__ topic,
                float* __restrict__ out_w)
{
    const int b    = blockIdx.x;
    const int part = blockIdx.y;
    const int t    = threadIdx.x;

    float mg = -FLT_MAX;
    #pragma unroll
    for (int i = 0; i < NSPLIT; ++i)
        mg = fmaxf(mg, g_mzpart[(b * NSPLIT + i) * 2 + 0]);

    float Zg = 0.f;
    float wsc[NSPLIT];
    #pragma unroll
    for (int i = 0; i < NSPLIT; ++i) {
        float mi = g_mzpart[(b * NSPLIT + i) * 2 + 0];
        float zi = g_mzpart[(b * NSPLIT + i) * 2 + 1];
        wsc[i] = __expf(mi - mg);
        Zg += zi * wsc[i];
    }
    const float inv = 1.f / Zg;

    if (part == 0) {
        float4 c = make_float4(0.f, 0.f, 0.f, 0.f);
        #pragma unroll
        for (int i = 0; i < NSPLIT; ++i) {
            float4 cp = ((const float4*)(g_cpart + ((size_t)b * NSPLIT + i) * HID))[t];
            c.x += wsc[i] * cp.x;  c.y += wsc[i] * cp.y;
            c.z += wsc[i] * cp.z;  c.w += wsc[i] * cp.w;
        }
        c.x *= inv; c.y *= inv; c.z *= inv; c.w *= inv;

        ((float4*)(g_cat + (size_t)b * CATK))[t] = c;
        ((float4*)(g_cat + (size_t)b * CATK + HID))[t] =
            ((const float4*)(x + (size_t)b * HID))[t];
        if (t < TOP / 4)
            ((float4*)(g_cat + (size_t)b * CATK + 2 * HID))[t] =
                ((const float4*)(topic + (size_t)b * TOP))[t];
    } else {
        // quarter q of this batch's weights: 1024 floats = 256 float4
        const int q = part - 1;
        const float4* sc = (const float4*)(g_scores + (size_t)b * SEQ + q * (SEQ / 4));
        float4*       ow = (float4*)(out_w + (size_t)b * SEQ + q * (SEQ / 4));
        float4 s = sc[t];
        float4 w;
        w.x = __expf(s.x - mg) * inv;
        w.y = __expf(s.y - mg) * inv;
        w.z = __expf(s.z - mg) * inv;
        w.w = __expf(s.w - mg) * inv;
        ow[t] = w;
    }
}

// ---------------------------------------------------------------------------
extern "C" void kernel_launch(void* const* d_in, const int* in_sizes, int n_in,
                              void* d_out, int out_size)
{
    const float* x     = (const float*)d_in[0];
    const float* ctx   = (const float*)d_in[1];
    const float* topic = (const float*)d_in[2];
    const float* W_in  = (const float*)d_in[3];
    const float* b_in  = (const float*)d_in[4];
    const float* W_out = (const float*)d_in[5];
    const float* b_out = (const float*)d_in[6];

    float* out  = (float*)d_out;                 // [BATCH,HID] output
    float* outw = out + BATCH * HID;             // [BATCH,SEQ] weights

    float* gamma_ptr;
    cudaGetSymbolAddress((void**)&gamma_ptr, g_gamma);
    float* cat_ptr;
    cudaGetSymbolAddress((void**)&cat_ptr, g_cat);

    static int smem_set = 0;
    if (!smem_set) {
        cudaFuncSetAttribute(attn_pass_kernel,
                             cudaFuncAttributeMaxDynamicSharedMemorySize,
                             ATTN_SMEM);
        smem_set = 1;
    }

    // 1) gamma = x @ W_in^T + b_in
    small_gemm_kernel<<<dim3(HID / 16, 2), 256>>>(x, W_in, b_in, gamma_ptr,
                                                  HID, HID, 0);

    // 2) fused scores + online softmax + partial c_t (single context pass)
    attn_pass_kernel<<<dim3(NSPLIT, BATCH), 256, ATTN_SMEM>>>(ctx);

    // 3) cross-split reduce + cat build + weights (parallel)
    reduce_c_kernel<<<dim3(BATCH, 5), 256>>>(x, topic, outw);

    // 4) output = tanh(cat @ W_out^T + b_out)
    small_gemm_kernel<<<dim3(HID / 16, 2), 256>>>(cat_ptr, W_out, b_out, out,
                                                  CATK, HID, 1);
}

// round 8
// speedup vs baseline: 1.7263x; 1.0164x over previous
#include <cuda_runtime.h>
#include <cuda_bf16.h>
#include <float.h>
#include <cstdint>

// Problem shape (fixed per reference)
#define BATCH 32
#define SEQ   4096
#define HID   1024
#define TOP   512
#define CATK  (2*HID + TOP)   // 2560

#define NSPLIT 16                        // S-splits per batch in attention pass
#define ROWS_PER_SPLIT (SEQ / NSPLIT)    // 256 rows per CTA
#define WARPS 8
#define ROWS_PER_WARP (ROWS_PER_SPLIT / WARPS)  // 32 rows per warp
#define VPL 8                            // float4 per lane per row (1024/4/32)
#define ATTN_SMEM (WARPS * 2 * 256 * 16) // 64 KB: per-warp double row buffer

#define GEMM_BH 16                       // batches per GEMM CTA (2 halves)

// ---------------- scratch (__device__ globals; no allocations) --------------
__device__ float g_gamma [BATCH * HID];
__device__ float g_scores[BATCH * SEQ];
__device__ float g_cpart [BATCH * NSPLIT * HID];
__device__ float g_mzpart[BATCH * NSPLIT * 2];
__device__ float g_cat   [BATCH * CATK];

__device__ __forceinline__ float dot4(float4 a, float4 b)
{
    return a.x * b.x + a.y * b.y + a.z * b.z + a.w * b.w;
}

// ---------------------------------------------------------------------------
// Kernel 1: small GEMM  out[b][h] = act( bias[h] + sum_k in[b][k]*W[h][k] )
// grid = (Hout/16, 2), block = 256. Warp owns 2 h rows; CTA one 16-batch half.
// W register-prefetched one chunk ahead; x tile cp.async double-buffered.
// K must be a multiple of 256 and >= 512.
// ---------------------------------------------------------------------------
__device__ __forceinline__ void stage_tile(uint32_t dst, const float* __restrict__ in,
                                           int b0, int K, int k0, int t)
{
    #pragma unroll
    for (int i = 0; i < 4; ++i) {
        int idx = t + i * 256;              // 1024 float4 total (16 KB)
        int bb  = idx >> 6;
        int kk  = idx & 63;
        const float4* src = (const float4*)(in + (size_t)(b0 + bb) * K + k0) + kk;
        asm volatile("cp.async.cg.shared.global [%0], [%1], 16;\n"
                     :: "r"(dst + idx * 16), "l"(src));
    }
}

__global__ void __launch_bounds__(256)
small_gemm_kernel(const float* __restrict__ in, const float* __restrict__ W,
                  const float* __restrict__ bias, float* __restrict__ out,
                  int K, int Hout, int act)
{
    __shared__ float4 tile[2][GEMM_BH * 64];   // double-buffered, 32 KB
    const int t    = threadIdx.x;
    const int warp = t >> 5;
    const int lane = t & 31;
    const int h0   = blockIdx.x * 16 + warp * 2;
    const int h1   = h0 + 1;
    const int b0   = blockIdx.y * GEMM_BH;
    const int N    = K / 256;                  // chunks (4 or 10)

    const uint32_t tbase = (uint32_t)__cvta_generic_to_shared(tile);

    // prologue: stage chunks 0,1
    stage_tile(tbase,         in, b0, K, 0,   t);
    asm volatile("cp.async.commit_group;\n");
    stage_tile(tbase + 16384, in, b0, K, 256, t);
    asm volatile("cp.async.commit_group;\n");

    const float4* W0 = (const float4*)(W + (size_t)h0 * K);   // 64 float4/chunk
    const float4* W1 = (const float4*)(W + (size_t)h1 * K);

    // current-chunk W registers (chunk 0)
    float4 wa0 = W0[lane], wa1 = W0[32 + lane];
    float4 wb0 = W1[lane], wb1 = W1[32 + lane];

    float acc0[GEMM_BH], acc1[GEMM_BH];
    #pragma unroll
    for (int b = 0; b < GEMM_BH; ++b) { acc0[b] = 0.f; acc1[b] = 0.f; }

    for (int ci = 0; ci < N; ++ci) {
        // prefetch next chunk's W into registers (overlaps with FFMA below)
        float4 na0 = make_float4(0,0,0,0), na1 = na0, nb0 = na0, nb1 = na0;
        if (ci + 1 < N) {
            const float4* p0 = W0 + (ci + 1) * 64;
            const float4* p1 = W1 + (ci + 1) * 64;
            na0 = p0[lane]; na1 = p0[32 + lane];
            nb0 = p1[lane]; nb1 = p1[32 + lane];
        }

        asm volatile("cp.async.wait_group 1;\n");
        __syncthreads();                       // tile[ci&1] ready

        const float4* tl = tile[ci & 1];
        #pragma unroll
        for (int bb = 0; bb < GEMM_BH; ++bb) {
            float4 xv = tl[bb * 64 + lane];
            acc0[bb] += dot4(wa0, xv);
            acc1[bb] += dot4(wb0, xv);
        }
        #pragma unroll
        for (int bb = 0; bb < GEMM_BH; ++bb) {
            float4 xv = tl[bb * 64 + 32 + lane];
            acc0[bb] += dot4(wa1, xv);
            acc1[bb] += dot4(wb1, xv);
        }
        __syncthreads();                       // all reads done before restage

        if (ci + 2 < N)
            stage_tile(tbase + (ci & 1) * 16384, in, b0, K, (ci + 2) * 256, t);
        asm volatile("cp.async.commit_group;\n");   // empty group ok

        wa0 = na0; wa1 = na1; wb0 = nb0; wb1 = nb1;
    }

    #pragma unroll
    for (int off = 16; off; off >>= 1)
        #pragma unroll
        for (int bb = 0; bb < GEMM_BH; ++bb) {
            acc0[bb] += __shfl_xor_sync(0xFFFFFFFFu, acc0[bb], off);
            acc1[bb] += __shfl_xor_sync(0xFFFFFFFFu, acc1[bb], off);
        }

    // epilogue: lanes 0-15 write h0 (batch = lane), lanes 16-31 write h1
    const int bl = lane & 15;
    float v = (lane < 16) ? acc0[bl] : acc1[bl];
    const int h = (lane < 16) ? h0 : h1;
    v += bias[h];
    if (act) v = tanhf(v);
    out[(size_t)(b0 + bl) * Hout + h] = v;
}

// ---------------------------------------------------------------------------
// Kernel 2: warp-autonomous fused scores + online softmax + weighted sum,
// with cp.async double-buffered row staging. grid = (NSPLIT, BATCH), block=256.
// ---------------------------------------------------------------------------
__device__ __forceinline__ void stage_row(uint32_t dst_base, const float4* src)
{
    #pragma unroll
    for (int i = 0; i < VPL; ++i)
        asm volatile("cp.async.cg.shared.global [%0], [%1], 16;\n"
                     :: "r"(dst_base + i * 512), "l"(src + i * 32));
}

__global__ void __launch_bounds__(256, 2)
attn_pass_kernel(const float* __restrict__ ctx)
{
    extern __shared__ float4 sbuf[];          // [WARPS][2][256] float4
    __shared__ float s_m[WARPS], s_Z[WARPS];

    const int t     = threadIdx.x;
    const int warp  = t >> 5;
    const int lane  = t & 31;
    const int split = blockIdx.x;
    const int b     = blockIdx.y;

    float4 g[VPL];
    {
        const float4* gp = (const float4*)(g_gamma + (size_t)b * HID);
        #pragma unroll
        for (int i = 0; i < VPL; ++i) g[i] = gp[lane + 32 * i];
    }

    const int row0 = split * ROWS_PER_SPLIT + warp * ROWS_PER_WARP;
    const float4* base = (const float4*)(ctx + ((size_t)b * SEQ + row0) * HID);

    float4* wbuf = sbuf + warp * 2 * 256;
    const uint32_t wbuf_addr =
        (uint32_t)__cvta_generic_to_shared(wbuf) + (uint32_t)lane * 16;

    #pragma unroll
    for (int pre = 0; pre < 2; ++pre) {
        stage_row(wbuf_addr + pre * 4096, base + pre * 256 + lane);
        asm volatile("cp.async.commit_group;\n");
    }

    float  m = -FLT_MAX, Z = 0.f;
    float4 c[VPL];
    #pragma unroll
    for (int i = 0; i < VPL; ++i) c[i] = make_float4(0.f, 0.f, 0.f, 0.f);

    for (int r = 0; r < ROWS_PER_WARP; ++r) {
        asm volatile("cp.async.wait_group 1;\n");
        __syncwarp();

        const float4* vbuf = wbuf + (r & 1) * 256;
        float4 v[VPL];
        #pragma unroll
        for (int i = 0; i < VPL; ++i) v[i] = vbuf[lane + 32 * i];
        __syncwarp();

        if (r + 2 < ROWS_PER_WARP)
            stage_row(wbuf_addr + (r & 1) * 4096, base + (r + 2) * 256 + lane);
        asm volatile("cp.async.commit_group;\n");

        float p = 0.f;
        #pragma unroll
        for (int i = 0; i < VPL; ++i)
            p += v[i].x * g[i].x + v[i].y * g[i].y + v[i].z * g[i].z + v[i].w * g[i].w;

        #pragma unroll
        for (int off = 16; off; off >>= 1)
            p += __shfl_xor_sync(0xFFFFFFFFu, p, off);

        if (lane == 0) g_scores[(size_t)b * SEQ + row0 + r] = p;

        if (p > m) {
            const float scale = __expf(m - p);
            Z *= scale;
            #pragma unroll
            for (int i = 0; i < VPL; ++i) {
                c[i].x *= scale; c[i].y *= scale;
                c[i].z *= scale; c[i].w *= scale;
            }
            m = p;
        }
        const float e = __expf(p - m);
        Z += e;
        #pragma unroll
        for (int i = 0; i < VPL; ++i) {
            c[i].x += e * v[i].x;  c[i].y += e * v[i].y;
            c[i].z += e * v[i].z;  c[i].w += e * v[i].w;
        }
    }

    asm volatile("cp.async.wait_group 0;\n");
    __syncthreads();
    float* s_c = (float*)sbuf;
    #pragma unroll
    for (int i = 0; i < VPL; ++i)
        ((float4*)(s_c + warp * HID))[lane + 32 * i] = c[i];
    if (lane == 0) { s_m[warp] = m; s_Z[warp] = Z; }
    __syncthreads();

    float mg = s_m[0];
    #pragma unroll
    for (int w = 1; w < WARPS; ++w) mg = fmaxf(mg, s_m[w]);

    float wsc[WARPS], Zg = 0.f;
    #pragma unroll
    for (int w = 0; w < WARPS; ++w) {
        wsc[w] = __expf(s_m[w] - mg);
        Zg += s_Z[w] * wsc[w];
    }

    float4 acc = make_float4(0.f, 0.f, 0.f, 0.f);
    #pragma unroll
    for (int w = 0; w < WARPS; ++w) {
        float4 cw = ((const float4*)(s_c + w * HID))[t];
        acc.x += wsc[w] * cw.x;  acc.y += wsc[w] * cw.y;
        acc.z += wsc[w] * cw.z;  acc.w += wsc[w] * cw.w;
    }
    ((float4*)(g_cpart + ((size_t)b * NSPLIT + split) * HID))[t] = acc;
    if (t == 0) {
        g_mzpart[(b * NSPLIT + split) * 2 + 0] = mg;
        g_mzpart[(b * NSPLIT + split) * 2 + 1] = Zg;
    }
}

// ---------------------------------------------------------------------------
// Kernel 3: cross-split reduce + cat build + weights, parallelized.
// grid = (BATCH, 5): y=0 -> c_t/cat; y=1..4 -> quarter of the weights row.
// ---------------------------------------------------------------------------
__global__ void __launch_bounds__(256)
reduce_c_kernel(const float* __restrict__ x, const float* __restrict__ topic,
                float* __restrict__ out_w)
{
    const int b    = blockIdx.x;
    const int part = blockIdx.y;
    const int t    = threadIdx.x;

    float mg = -FLT_MAX;
    #pragma unroll
    for (int i = 0; i < NSPLIT; ++i)
        mg = fmaxf(mg, g_mzpart[(b * NSPLIT + i) * 2 + 0]);

    float Zg = 0.f;
    float wsc[NSPLIT];
    #pragma unroll
    for (int i = 0; i < NSPLIT; ++i) {
        float mi = g_mzpart[(b * NSPLIT + i) * 2 + 0];
        float zi = g_mzpart[(b * NSPLIT + i) * 2 + 1];
        wsc[i] = __expf(mi - mg);
        Zg += zi * wsc[i];
    }
    const float inv = 1.f / Zg;

    if (part == 0) {
        float4 c = make_float4(0.f, 0.f, 0.f, 0.f);
        #pragma unroll
        for (int i = 0; i < NSPLIT; ++i) {
            float4 cp = ((const float4*)(g_cpart + ((size_t)b * NSPLIT + i) * HID))[t];
            c.x += wsc[i] * cp.x;  c.y += wsc[i] * cp.y;
            c.z += wsc[i] * cp.z;  c.w += wsc[i] * cp.w;
        }
        c.x *= inv; c.y *= inv; c.z *= inv; c.w *= inv;

        ((float4*)(g_cat + (size_t)b * CATK))[t] = c;
        ((float4*)(g_cat + (size_t)b * CATK + HID))[t] =
            ((const float4*)(x + (size_t)b * HID))[t];
        if (t < TOP / 4)
            ((float4*)(g_cat + (size_t)b * CATK + 2 * HID))[t] =
                ((const float4*)(topic + (size_t)b * TOP))[t];
    } else {
        const int q = part - 1;
        const float4* sc = (const float4*)(g_scores + (size_t)b * SEQ + q * (SEQ / 4));
        float4*       ow = (float4*)(out_w + (size_t)b * SEQ + q * (SEQ / 4));
        float4 s = sc[t];
        float4 w;
        w.x = __expf(s.x - mg) * inv;
        w.y = __expf(s.y - mg) * inv;
        w.z = __expf(s.z - mg) * inv;
        w.w = __expf(s.w - mg) * inv;
        ow[t] = w;
    }
}

// ---------------------------------------------------------------------------
extern "C" void kernel_launch(void* const* d_in, const int* in_sizes, int n_in,
                              void* d_out, int out_size)
{
    const float* x     = (const float*)d_in[0];
    const float* ctx   = (const float*)d_in[1];
    const float* topic = (const float*)d_in[2];
    const float* W_in  = (const float*)d_in[3];
    const float* b_in  = (const float*)d_in[4];
    const float* W_out = (const float*)d_in[5];
    const float* b_out = (const float*)d_in[6];

    float* out  = (float*)d_out;                 // [BATCH,HID] output
    float* outw = out + BATCH * HID;             // [BATCH,SEQ] weights

    float* gamma_ptr;
    cudaGetSymbolAddress((void**)&gamma_ptr, g_gamma);
    float* cat_ptr;
    cudaGetSymbolAddress((void**)&cat_ptr, g_cat);

    static int smem_set = 0;
    if (!smem_set) {
        cudaFuncSetAttribute(attn_pass_kernel,
                             cudaFuncAttributeMaxDynamicSharedMemorySize,
                             ATTN_SMEM);
        smem_set = 1;
    }

    // 1) gamma = x @ W_in^T + b_in
    small_gemm_kernel<<<dim3(HID / 16, 2), 256>>>(x, W_in, b_in, gamma_ptr,
                                                  HID, HID, 0);

    // 2) fused scores + online softmax + partial c_t (single context pass)
    attn_pass_kernel<<<dim3(NSPLIT, BATCH), 256, ATTN_SMEM>>>(ctx);

    // 3) cross-split reduce + cat build + weights (parallel)
    reduce_c_kernel<<<dim3(BATCH, 5), 256>>>(x, topic, outw);

    // 4) output = tanh(cat @ W_out^T + b_out)
    small_gemm_kernel<<<dim3(HID / 16, 2), 256>>>(cat_ptr, W_out, b_out, out,
                                                  CATK, HID, 1);
}

// round 9
// speedup vs baseline: 1.8147x; 1.0512x over previous
#include <cuda_runtime.h>
#include <cuda_bf16.h>
#include <float.h>
#include <cstdint>

// Problem shape (fixed per reference)
#define BATCH 32
#define SEQ   4096
#define HID   1024
#define TOP   512
#define CATK  (2*HID + TOP)   // 2560

#define NSPLIT 16                        // S-splits per batch in attention pass
#define ROWS_PER_SPLIT (SEQ / NSPLIT)    // 256 rows per CTA
#define WARPS 8
#define ROWS_PER_WARP (ROWS_PER_SPLIT / WARPS)  // 32 rows per warp
#define VPL 8                            // float4 per lane per row (1024/4/32)
#define ATTN_SMEM (WARPS * 2 * 256 * 16) // 64 KB: per-warp double row buffer

#define GEMM_BH 8                        // batches per GEMM CTA (4 quarters)
#define GEMM_TILE_B (GEMM_BH * 64 * 16)  // bytes per tile buffer (8 KB)

// ---------------- scratch (__device__ globals; no allocations) --------------
__device__ float g_gamma [BATCH * HID];
__device__ float g_scores[BATCH * SEQ];
__device__ float g_cpart [BATCH * NSPLIT * HID];
__device__ float g_mzpart[BATCH * NSPLIT * 2];
__device__ float g_cat   [BATCH * CATK];

__device__ __forceinline__ float dot4(float4 a, float4 b)
{
    return a.x * b.x + a.y * b.y + a.z * b.z + a.w * b.w;
}

// ---------------------------------------------------------------------------
// Kernel 1: small GEMM  out[b][h] = act( bias[h] + sum_k in[b][k]*W[h][k] )
// grid = (Hout/16, 4), block = 256. Warp owns 2 h rows; CTA one 8-batch
// quarter. W register-prefetched one chunk ahead; x tile cp.async
// double-buffered. K must be a multiple of 256 and >= 512.
// ---------------------------------------------------------------------------
__device__ __forceinline__ void stage_tile(uint32_t dst, const float* __restrict__ in,
                                           int b0, int K, int k0, int t)
{
    #pragma unroll
    for (int i = 0; i < 2; ++i) {
        int idx = t + i * 256;              // 512 float4 total (8 KB)
        int bb  = idx >> 6;
        int kk  = idx & 63;
        const float4* src = (const float4*)(in + (size_t)(b0 + bb) * K + k0) + kk;
        asm volatile("cp.async.cg.shared.global [%0], [%1], 16;\n"
                     :: "r"(dst + idx * 16), "l"(src));
    }
}

__global__ void __launch_bounds__(256)
small_gemm_kernel(const float* __restrict__ in, const float* __restrict__ W,
                  const float* __restrict__ bias, float* __restrict__ out,
                  int K, int Hout, int act)
{
    __shared__ float4 tile[2][GEMM_BH * 64];   // double-buffered, 16 KB
    const int t    = threadIdx.x;
    const int warp = t >> 5;
    const int lane = t & 31;
    const int h0   = blockIdx.x * 16 + warp * 2;
    const int h1   = h0 + 1;
    const int b0   = blockIdx.y * GEMM_BH;
    const int N    = K / 256;                  // chunks (4 or 10)

    const uint32_t tbase = (uint32_t)__cvta_generic_to_shared(tile);

    // prologue: stage chunks 0,1
    stage_tile(tbase,               in, b0, K, 0,   t);
    asm volatile("cp.async.commit_group;\n");
    stage_tile(tbase + GEMM_TILE_B, in, b0, K, 256, t);
    asm volatile("cp.async.commit_group;\n");

    const float4* W0 = (const float4*)(W + (size_t)h0 * K);   // 64 float4/chunk
    const float4* W1 = (const float4*)(W + (size_t)h1 * K);

    // current-chunk W registers (chunk 0)
    float4 wa0 = W0[lane], wa1 = W0[32 + lane];
    float4 wb0 = W1[lane], wb1 = W1[32 + lane];

    float acc0[GEMM_BH], acc1[GEMM_BH];
    #pragma unroll
    for (int b = 0; b < GEMM_BH; ++b) { acc0[b] = 0.f; acc1[b] = 0.f; }

    for (int ci = 0; ci < N; ++ci) {
        // prefetch next chunk's W into registers (overlaps with FFMA below)
        float4 na0 = make_float4(0,0,0,0), na1 = na0, nb0 = na0, nb1 = na0;
        if (ci + 1 < N) {
            const float4* p0 = W0 + (ci + 1) * 64;
            const float4* p1 = W1 + (ci + 1) * 64;
            na0 = p0[lane]; na1 = p0[32 + lane];
            nb0 = p1[lane]; nb1 = p1[32 + lane];
        }

        asm volatile("cp.async.wait_group 1;\n");
        __syncthreads();                       // tile[ci&1] ready

        const float4* tl = tile[ci & 1];
        #pragma unroll
        for (int bb = 0; bb < GEMM_BH; ++bb) {
            float4 xv = tl[bb * 64 + lane];
            acc0[bb] += dot4(wa0, xv);
            acc1[bb] += dot4(wb0, xv);
        }
        #pragma unroll
        for (int bb = 0; bb < GEMM_BH; ++bb) {
            float4 xv = tl[bb * 64 + 32 + lane];
            acc0[bb] += dot4(wa1, xv);
            acc1[bb] += dot4(wb1, xv);
        }
        __syncthreads();                       // all reads done before restage

        if (ci + 2 < N)
            stage_tile(tbase + (ci & 1) * GEMM_TILE_B, in, b0, K, (ci + 2) * 256, t);
        asm volatile("cp.async.commit_group;\n");   // empty group ok

        wa0 = na0; wa1 = na1; wb0 = nb0; wb1 = nb1;
    }

    #pragma unroll
    for (int off = 16; off; off >>= 1)
        #pragma unroll
        for (int bb = 0; bb < GEMM_BH; ++bb) {
            acc0[bb] += __shfl_xor_sync(0xFFFFFFFFu, acc0[bb], off);
            acc1[bb] += __shfl_xor_sync(0xFFFFFFFFu, acc1[bb], off);
        }

    // epilogue: lanes 0-7 write h0 (batch = lane), lanes 8-15 write h1
    if (lane < 16) {
        const int bl = lane & 7;
        float v = (lane < 8) ? acc0[bl] : acc1[bl];
        const int h = (lane < 8) ? h0 : h1;
        v += bias[h];
        if (act) v = tanhf(v);
        out[(size_t)(b0 + bl) * Hout + h] = v;
    }
}

// ---------------------------------------------------------------------------
// Kernel 2: warp-autonomous fused scores + online softmax + weighted sum,
// with cp.async double-buffered row staging. grid = (NSPLIT, BATCH), block=256.
// ---------------------------------------------------------------------------
__device__ __forceinline__ void stage_row(uint32_t dst_base, const float4* src)
{
    #pragma unroll
    for (int i = 0; i < VPL; ++i)
        asm volatile("cp.async.cg.shared.global [%0], [%1], 16;\n"
                     :: "r"(dst_base + i * 512), "l"(src + i * 32));
}

__global__ void __launch_bounds__(256, 2)
attn_pass_kernel(const float* __restrict__ ctx)
{
    extern __shared__ float4 sbuf[];          // [WARPS][2][256] float4
    __shared__ float s_m[WARPS], s_Z[WARPS];

    const int t     = threadIdx.x;
    const int warp  = t >> 5;
    const int lane  = t & 31;
    const int split = blockIdx.x;
    const int b     = blockIdx.y;

    float4 g[VPL];
    {
        const float4* gp = (const float4*)(g_gamma + (size_t)b * HID);
        #pragma unroll
        for (int i = 0; i < VPL; ++i) g[i] = gp[lane + 32 * i];
    }

    const int row0 = split * ROWS_PER_SPLIT + warp * ROWS_PER_WARP;
    const float4* base = (const float4*)(ctx + ((size_t)b * SEQ + row0) * HID);

    float4* wbuf = sbuf + warp * 2 * 256;
    const uint32_t wbuf_addr =
        (uint32_t)__cvta_generic_to_shared(wbuf) + (uint32_t)lane * 16;

    #pragma unroll
    for (int pre = 0; pre < 2; ++pre) {
        stage_row(wbuf_addr + pre * 4096, base + pre * 256 + lane);
        asm volatile("cp.async.commit_group;\n");
    }

    float  m = -FLT_MAX, Z = 0.f;
    float4 c[VPL];
    #pragma unroll
    for (int i = 0; i < VPL; ++i) c[i] = make_float4(0.f, 0.f, 0.f, 0.f);

    for (int r = 0; r < ROWS_PER_WARP; ++r) {
        asm volatile("cp.async.wait_group 1;\n");
        __syncwarp();

        const float4* vbuf = wbuf + (r & 1) * 256;
        float4 v[VPL];
        #pragma unroll
        for (int i = 0; i < VPL; ++i) v[i] = vbuf[lane + 32 * i];
        __syncwarp();

        if (r + 2 < ROWS_PER_WARP)
            stage_row(wbuf_addr + (r & 1) * 4096, base + (r + 2) * 256 + lane);
        asm volatile("cp.async.commit_group;\n");

        float p = 0.f;
        #pragma unroll
        for (int i = 0; i < VPL; ++i)
            p += v[i].x * g[i].x + v[i].y * g[i].y + v[i].z * g[i].z + v[i].w * g[i].w;

        #pragma unroll
        for (int off = 16; off; off >>= 1)
            p += __shfl_xor_sync(0xFFFFFFFFu, p, off);

        if (lane == 0) g_scores[(size_t)b * SEQ + row0 + r] = p;

        if (p > m) {
            const float scale = __expf(m - p);
            Z *= scale;
            #pragma unroll
            for (int i = 0; i < VPL; ++i) {
                c[i].x *= scale; c[i].y *= scale;
                c[i].z *= scale; c[i].w *= scale;
            }
            m = p;
        }
        const float e = __expf(p - m);
        Z += e;
        #pragma unroll
        for (int i = 0; i < VPL; ++i) {
            c[i].x += e * v[i].x;  c[i].y += e * v[i].y;
            c[i].z += e * v[i].z;  c[i].w += e * v[i].w;
        }
    }

    asm volatile("cp.async.wait_group 0;\n");
    __syncthreads();
    float* s_c = (float*)sbuf;
    #pragma unroll
    for (int i = 0; i < VPL; ++i)
        ((float4*)(s_c + warp * HID))[lane + 32 * i] = c[i];
    if (lane == 0) { s_m[warp] = m; s_Z[warp] = Z; }
    __syncthreads();

    float mg = s_m[0];
    #pragma unroll
    for (int w = 1; w < WARPS; ++w) mg = fmaxf(mg, s_m[w]);

    float wsc[WARPS], Zg = 0.f;
    #pragma unroll
    for (int w = 0; w < WARPS; ++w) {
        wsc[w] = __expf(s_m[w] - mg);
        Zg += s_Z[w] * wsc[w];
    }

    float4 acc = make_float4(0.f, 0.f, 0.f, 0.f);
    #pragma unroll
    for (int w = 0; w < WARPS; ++w) {
        float4 cw = ((const float4*)(s_c + w * HID))[t];
        acc.x += wsc[w] * cw.x;  acc.y += wsc[w] * cw.y;
        acc.z += wsc[w] * cw.z;  acc.w += wsc[w] * cw.w;
    }
    ((float4*)(g_cpart + ((size_t)b * NSPLIT + split) * HID))[t] = acc;
    if (t == 0) {
        g_mzpart[(b * NSPLIT + split) * 2 + 0] = mg;
        g_mzpart[(b * NSPLIT + split) * 2 + 1] = Zg;
    }
}

// ---------------------------------------------------------------------------
// Kernel 3: cross-split reduce + cat build + weights, parallelized.
// grid = (BATCH, 5): y=0 -> c_t/cat; y=1..4 -> quarter of the weights row.
// ---------------------------------------------------------------------------
__global__ void __launch_bounds__(256)
reduce_c_kernel(const float* __restrict__ x, const float* __restrict__ topic,
                float* __restrict__ out_w)
{
    const int b    = blockIdx.x;
    const int part = blockIdx.y;
    const int t    = threadIdx.x;

    float mg = -FLT_MAX;
    #pragma unroll
    for (int i = 0; i < NSPLIT; ++i)
        mg = fmaxf(mg, g_mzpart[(b * NSPLIT + i) * 2 + 0]);

    float Zg = 0.f;
    float wsc[NSPLIT];
    #pragma unroll
    for (int i = 0; i < NSPLIT; ++i) {
        float mi = g_mzpart[(b * NSPLIT + i) * 2 + 0];
        float zi = g_mzpart[(b * NSPLIT + i) * 2 + 1];
        wsc[i] = __expf(mi - mg);
        Zg += zi * wsc[i];
    }
    const float inv = 1.f / Zg;

    if (part == 0) {
        float4 c = make_float4(0.f, 0.f, 0.f, 0.f);
        #pragma unroll
        for (int i = 0; i < NSPLIT; ++i) {
            float4 cp = ((const float4*)(g_cpart + ((size_t)b * NSPLIT + i) * HID))[t];
            c.x += wsc[i] * cp.x;  c.y += wsc[i] * cp.y;
            c.z += wsc[i] * cp.z;  c.w += wsc[i] * cp.w;
        }
        c.x *= inv; c.y *= inv; c.z *= inv; c.w *= inv;

        ((float4*)(g_cat + (size_t)b * CATK))[t] = c;
        ((float4*)(g_cat + (size_t)b * CATK + HID))[t] =
            ((const float4*)(x + (size_t)b * HID))[t];
        if (t < TOP / 4)
            ((float4*)(g_cat + (size_t)b * CATK + 2 * HID))[t] =
                ((const float4*)(topic + (size_t)b * TOP))[t];
    } else {
        const int q = part - 1;
        const float4* sc = (const float4*)(g_scores + (size_t)b * SEQ + q * (SEQ / 4));
        float4*       ow = (float4*)(out_w + (size_t)b * SEQ + q * (SEQ / 4));
        float4 s = sc[t];
        float4 w;
        w.x = __expf(s.x - mg) * inv;
        w.y = __expf(s.y - mg) * inv;
        w.z = __expf(s.z - mg) * inv;
        w.w = __expf(s.w - mg) * inv;
        ow[t] = w;
    }
}

// ---------------------------------------------------------------------------
extern "C" void kernel_launch(void* const* d_in, const int* in_sizes, int n_in,
                              void* d_out, int out_size)
{
    const float* x     = (const float*)d_in[0];
    const float* ctx   = (const float*)d_in[1];
    const float* topic = (const float*)d_in[2];
    const float* W_in  = (const float*)d_in[3];
    const float* b_in  = (const float*)d_in[4];
    const float* W_out = (const float*)d_in[5];
    const float* b_out = (const float*)d_in[6];

    float* out  = (float*)d_out;                 // [BATCH,HID] output
    float* outw = out + BATCH * HID;             // [BATCH,SEQ] weights

    float* gamma_ptr;
    cudaGetSymbolAddress((void**)&gamma_ptr, g_gamma);
    float* cat_ptr;
    cudaGetSymbolAddress((void**)&cat_ptr, g_cat);

    static int smem_set = 0;
    if (!smem_set) {
        cudaFuncSetAttribute(attn_pass_kernel,
                             cudaFuncAttributeMaxDynamicSharedMemorySize,
                             ATTN_SMEM);
        smem_set = 1;
    }

    // 1) gamma = x @ W_in^T + b_in
    small_gemm_kernel<<<dim3(HID / 16, 4), 256>>>(x, W_in, b_in, gamma_ptr,
                                                  HID, HID, 0);

    // 2) fused scores + online softmax + partial c_t (single context pass)
    attn_pass_kernel<<<dim3(NSPLIT, BATCH), 256, ATTN_SMEM>>>(ctx);

    // 3) cross-split reduce + cat build + weights (parallel)
    reduce_c_kernel<<<dim3(BATCH, 5), 256>>>(x, topic, outw);

    // 4) output = tanh(cat @ W_out^T + b_out)
    small_gemm_kernel<<<dim3(HID / 16, 4), 256>>>(cat_ptr, W_out, b_out, out,
                                                  CATK, HID, 1);
}

// round 10
// speedup vs baseline: 1.8214x; 1.0037x over previous
#include <cuda_runtime.h>
#include <cuda_bf16.h>
#include <float.h>
#include <cstdint>

// Problem shape (fixed per reference)
#define BATCH 32
#define SEQ   4096
#define HID   1024
#define TOP   512
#define CATK  (2*HID + TOP)   // 2560

#define NSPLIT 16                        // S-splits per batch in attention pass
#define ROWS_PER_SPLIT (SEQ / NSPLIT)    // 256 rows per CTA
#define WARPS 8
#define ROWS_PER_WARP (ROWS_PER_SPLIT / WARPS)  // 32 rows per warp
#define VPL 8                            // float4 per lane per row (1024/4/32)
#define ATTN_SMEM (WARPS * 2 * 256 * 16) // 64 KB: per-warp double row buffer

#define GEMM_BH 4                        // batches per GEMM CTA (8 slices)
#define GEMM_HW 4                        // h-rows per warp
#define GEMM_TILE_B (GEMM_BH * 64 * 16)  // bytes per tile buffer (4 KB)

// ---------------- scratch (__device__ globals; no allocations) --------------
__device__ float g_gamma [BATCH * HID];
__device__ float g_scores[BATCH * SEQ];
__device__ float g_cpart [BATCH * NSPLIT * HID];
__device__ float g_mzpart[BATCH * NSPLIT * 2];
__device__ float g_cat   [BATCH * CATK];

__device__ __forceinline__ float dot4(float4 a, float4 b)
{
    return a.x * b.x + a.y * b.y + a.z * b.z + a.w * b.w;
}

// ---------------------------------------------------------------------------
// Kernel 1: small GEMM  out[b][h] = act( bias[h] + sum_k in[b][k]*W[h][k] )
// grid = (Hout/32, 8), block = 256. Warp owns 4 h rows; CTA one 4-batch
// slice. Each smem x-read feeds 16 FFMA. W register-prefetched one chunk
// ahead; x tile cp.async double-buffered. K: multiple of 256, >= 512.
// ---------------------------------------------------------------------------
__device__ __forceinline__ void stage_tile(uint32_t dst, const float* __restrict__ in,
                                           int b0, int K, int k0, int t)
{
    // 256 float4 total (4 KB), one per thread
    int bb = t >> 6;
    int kk = t & 63;
    const float4* src = (const float4*)(in + (size_t)(b0 + bb) * K + k0) + kk;
    asm volatile("cp.async.cg.shared.global [%0], [%1], 16;\n"
                 :: "r"(dst + t * 16), "l"(src));
}

__global__ void __launch_bounds__(256)
small_gemm_kernel(const float* __restrict__ in, const float* __restrict__ W,
                  const float* __restrict__ bias, float* __restrict__ out,
                  int K, int Hout, int act)
{
    __shared__ float4 tile[2][GEMM_BH * 64];   // double-buffered, 8 KB
    const int t    = threadIdx.x;
    const int warp = t >> 5;
    const int lane = t & 31;
    const int hb   = blockIdx.x * 32 + warp * GEMM_HW;   // first h of this warp
    const int b0   = blockIdx.y * GEMM_BH;
    const int N    = K / 256;                  // chunks (4 or 10)

    const uint32_t tbase = (uint32_t)__cvta_generic_to_shared(tile);

    // prologue: stage chunks 0,1
    stage_tile(tbase,               in, b0, K, 0,   t);
    asm volatile("cp.async.commit_group;\n");
    stage_tile(tbase + GEMM_TILE_B, in, b0, K, 256, t);
    asm volatile("cp.async.commit_group;\n");

    const float4* Wp[GEMM_HW];
    #pragma unroll
    for (int h = 0; h < GEMM_HW; ++h)
        Wp[h] = (const float4*)(W + (size_t)(hb + h) * K);   // 64 float4/chunk

    // current-chunk W registers (chunk 0)
    float4 w[GEMM_HW][2];
    #pragma unroll
    for (int h = 0; h < GEMM_HW; ++h) {
        w[h][0] = Wp[h][lane];
        w[h][1] = Wp[h][32 + lane];
    }

    float acc[GEMM_HW][GEMM_BH];
    #pragma unroll
    for (int h = 0; h < GEMM_HW; ++h)
        #pragma unroll
        for (int b = 0; b < GEMM_BH; ++b) acc[h][b] = 0.f;

    for (int ci = 0; ci < N; ++ci) {
        // prefetch next chunk's W into registers (overlaps FFMA below)
        float4 nw[GEMM_HW][2];
        if (ci + 1 < N) {
            #pragma unroll
            for (int h = 0; h < GEMM_HW; ++h) {
                const float4* p = Wp[h] + (ci + 1) * 64;
                nw[h][0] = p[lane];
                nw[h][1] = p[32 + lane];
            }
        } else {
            #pragma unroll
            for (int h = 0; h < GEMM_HW; ++h)
                nw[h][0] = nw[h][1] = make_float4(0.f, 0.f, 0.f, 0.f);
        }

        asm volatile("cp.async.wait_group 1;\n");
        __syncthreads();                       // tile[ci&1] ready

        const float4* tl = tile[ci & 1];
        #pragma unroll
        for (int half = 0; half < 2; ++half)
            #pragma unroll
            for (int bb = 0; bb < GEMM_BH; ++bb) {
                float4 xv = tl[bb * 64 + half * 32 + lane];
                #pragma unroll
                for (int h = 0; h < GEMM_HW; ++h)
                    acc[h][bb] += dot4(w[h][half], xv);
            }
        __syncthreads();                       // all reads done before restage

        if (ci + 2 < N)
            stage_tile(tbase + (ci & 1) * GEMM_TILE_B, in, b0, K, (ci + 2) * 256, t);
        asm volatile("cp.async.commit_group;\n");   // empty group ok

        #pragma unroll
        for (int h = 0; h < GEMM_HW; ++h) {
            w[h][0] = nw[h][0];
            w[h][1] = nw[h][1];
        }
    }

    #pragma unroll
    for (int off = 16; off; off >>= 1)
        #pragma unroll
        for (int h = 0; h < GEMM_HW; ++h)
            #pragma unroll
            for (int bb = 0; bb < GEMM_BH; ++bb)
                acc[h][bb] += __shfl_xor_sync(0xFFFFFFFFu, acc[h][bb], off);

    // epilogue: lanes 0-15 each write one (h, b): h = lane>>2, b = lane&3
    if (lane < 16) {
        const int hl = lane >> 2;
        const int bl = lane & 3;
        float v = acc[hl][bl] + bias[hb + hl];
        if (act) v = tanhf(v);
        out[(size_t)(b0 + bl) * Hout + hb + hl] = v;
    }
}

// ---------------------------------------------------------------------------
// Kernel 2: warp-autonomous fused scores + online softmax + weighted sum,
// with cp.async double-buffered row staging. grid = (NSPLIT, BATCH), block=256.
// ---------------------------------------------------------------------------
__device__ __forceinline__ void stage_row(uint32_t dst_base, const float4* src)
{
    #pragma unroll
    for (int i = 0; i < VPL; ++i)
        asm volatile("cp.async.cg.shared.global [%0], [%1], 16;\n"
                     :: "r"(dst_base + i * 512), "l"(src + i * 32));
}

__global__ void __launch_bounds__(256, 2)
attn_pass_kernel(const float* __restrict__ ctx)
{
    extern __shared__ float4 sbuf[];          // [WARPS][2][256] float4
    __shared__ float s_m[WARPS], s_Z[WARPS];

    const int t     = threadIdx.x;
    const int warp  = t >> 5;
    const int lane  = t & 31;
    const int split = blockIdx.x;
    const int b     = blockIdx.y;

    float4 g[VPL];
    {
        const float4* gp = (const float4*)(g_gamma + (size_t)b * HID);
        #pragma unroll
        for (int i = 0; i < VPL; ++i) g[i] = gp[lane + 32 * i];
    }

    const int row0 = split * ROWS_PER_SPLIT + warp * ROWS_PER_WARP;
    const float4* base = (const float4*)(ctx + ((size_t)b * SEQ + row0) * HID);

    float4* wbuf = sbuf + warp * 2 * 256;
    const uint32_t wbuf_addr =
        (uint32_t)__cvta_generic_to_shared(wbuf) + (uint32_t)lane * 16;

    #pragma unroll
    for (int pre = 0; pre < 2; ++pre) {
        stage_row(wbuf_addr + pre * 4096, base + pre * 256 + lane);
        asm volatile("cp.async.commit_group;\n");
    }

    float  m = -FLT_MAX, Z = 0.f;
    float4 c[VPL];
    #pragma unroll
    for (int i = 0; i < VPL; ++i) c[i] = make_float4(0.f, 0.f, 0.f, 0.f);

    for (int r = 0; r < ROWS_PER_WARP; ++r) {
        asm volatile("cp.async.wait_group 1;\n");
        __syncwarp();

        const float4* vbuf = wbuf + (r & 1) * 256;
        float4 v[VPL];
        #pragma unroll
        for (int i = 0; i < VPL; ++i) v[i] = vbuf[lane + 32 * i];
        __syncwarp();

        if (r + 2 < ROWS_PER_WARP)
            stage_row(wbuf_addr + (r & 1) * 4096, base + (r + 2) * 256 + lane);
        asm volatile("cp.async.commit_group;\n");

        float p = 0.f;
        #pragma unroll
        for (int i = 0; i < VPL; ++i)
            p += v[i].x * g[i].x + v[i].y * g[i].y + v[i].z * g[i].z + v[i].w * g[i].w;

        #pragma unroll
        for (int off = 16; off; off >>= 1)
            p += __shfl_xor_sync(0xFFFFFFFFu, p, off);

        if (lane == 0) g_scores[(size_t)b * SEQ + row0 + r] = p;

        if (p > m) {
            const float scale = __expf(m - p);
            Z *= scale;
            #pragma unroll
            for (int i = 0; i < VPL; ++i) {
                c[i].x *= scale; c[i].y *= scale;
                c[i].z *= scale; c[i].w *= scale;
            }
            m = p;
        }
        const float e = __expf(p - m);
        Z += e;
        #pragma unroll
        for (int i = 0; i < VPL; ++i) {
            c[i].x += e * v[i].x;  c[i].y += e * v[i].y;
            c[i].z += e * v[i].z;  c[i].w += e * v[i].w;
        }
    }

    asm volatile("cp.async.wait_group 0;\n");
    __syncthreads();
    float* s_c = (float*)sbuf;
    #pragma unroll
    for (int i = 0; i < VPL; ++i)
        ((float4*)(s_c + warp * HID))[lane + 32 * i] = c[i];
    if (lane == 0) { s_m[warp] = m; s_Z[warp] = Z; }
    __syncthreads();

    float mg = s_m[0];
    #pragma unroll
    for (int w = 1; w < WARPS; ++w) mg = fmaxf(mg, s_m[w]);

    float wsc[WARPS], Zg = 0.f;
    #pragma unroll
    for (int w = 0; w < WARPS; ++w) {
        wsc[w] = __expf(s_m[w] - mg);
        Zg += s_Z[w] * wsc[w];
    }

    float4 acc = make_float4(0.f, 0.f, 0.f, 0.f);
    #pragma unroll
    for (int w = 0; w < WARPS; ++w) {
        float4 cw = ((const float4*)(s_c + w * HID))[t];
        acc.x += wsc[w] * cw.x;  acc.y += wsc[w] * cw.y;
        acc.z += wsc[w] * cw.z;  acc.w += wsc[w] * cw.w;
    }
    ((float4*)(g_cpart + ((size_t)b * NSPLIT + split) * HID))[t] = acc;
    if (t == 0) {
        g_mzpart[(b * NSPLIT + split) * 2 + 0] = mg;
        g_mzpart[(b * NSPLIT + split) * 2 + 1] = Zg;
    }
}

// ---------------------------------------------------------------------------
// Kernel 3: cross-split reduce + cat build + weights, parallelized.
// grid = (BATCH, 5): y=0 -> c_t/cat; y=1..4 -> quarter of the weights row.
// ---------------------------------------------------------------------------
__global__ void __launch_bounds__(256)
reduce_c_kernel(const float* __restrict__ x, const float* __restrict__ topic,
                float* __restrict__ out_w)
{
    const int b    = blockIdx.x;
    const int part = blockIdx.y;
    const int t    = threadIdx.x;

    float mg = -FLT_MAX;
    #pragma unroll
    for (int i = 0; i < NSPLIT; ++i)
        mg = fmaxf(mg, g_mzpart[(b * NSPLIT + i) * 2 + 0]);

    float Zg = 0.f;
    float wsc[NSPLIT];
    #pragma unroll
    for (int i = 0; i < NSPLIT; ++i) {
        float mi = g_mzpart[(b * NSPLIT + i) * 2 + 0];
        float zi = g_mzpart[(b * NSPLIT + i) * 2 + 1];
        wsc[i] = __expf(mi - mg);
        Zg += zi * wsc[i];
    }
    const float inv = 1.f / Zg;

    if (part == 0) {
        float4 c = make_float4(0.f, 0.f, 0.f, 0.f);
        #pragma unroll
        for (int i = 0; i < NSPLIT; ++i) {
            float4 cp = ((const float4*)(g_cpart + ((size_t)b * NSPLIT + i) * HID))[t];
            c.x += wsc[i] * cp.x;  c.y += wsc[i] * cp.y;
            c.z += wsc[i] * cp.z;  c.w += wsc[i] * cp.w;
        }
        c.x *= inv; c.y *= inv; c.z *= inv; c.w *= inv;

        ((float4*)(g_cat + (size_t)b * CATK))[t] = c;
        ((float4*)(g_cat + (size_t)b * CATK + HID))[t] =
            ((const float4*)(x + (size_t)b * HID))[t];
        if (t < TOP / 4)
            ((float4*)(g_cat + (size_t)b * CATK + 2 * HID))[t] =
                ((const float4*)(topic + (size_t)b * TOP))[t];
    } else {
        const int q = part - 1;
        const float4* sc = (const float4*)(g_scores + (size_t)b * SEQ + q * (SEQ / 4));
        float4*       ow = (float4*)(out_w + (size_t)b * SEQ + q * (SEQ / 4));
        float4 s = sc[t];
        float4 w;
        w.x = __expf(s.x - mg) * inv;
        w.y = __expf(s.y - mg) * inv;
        w.z = __expf(s.z - mg) * inv;
        w.w = __expf(s.w - mg) * inv;
        ow[t] = w;
    }
}

// ---------------------------------------------------------------------------
extern "C" void kernel_launch(void* const* d_in, const int* in_sizes, int n_in,
                              void* d_out, int out_size)
{
    const float* x     = (const float*)d_in[0];
    const float* ctx   = (const float*)d_in[1];
    const float* topic = (const float*)d_in[2];
    const float* W_in  = (const float*)d_in[3];
    const float* b_in  = (const float*)d_in[4];
    const float* W_out = (const float*)d_in[5];
    const float* b_out = (const float*)d_in[6];

    float* out  = (float*)d_out;                 // [BATCH,HID] output
    float* outw = out + BATCH * HID;             // [BATCH,SEQ] weights

    float* gamma_ptr;
    cudaGetSymbolAddress((void**)&gamma_ptr, g_gamma);
    float* cat_ptr;
    cudaGetSymbolAddress((void**)&cat_ptr, g_cat);

    static int smem_set = 0;
    if (!smem_set) {
        cudaFuncSetAttribute(attn_pass_kernel,
                             cudaFuncAttributeMaxDynamicSharedMemorySize,
                             ATTN_SMEM);
        smem_set = 1;
    }

    // 1) gamma = x @ W_in^T + b_in
    small_gemm_kernel<<<dim3(HID / 32, BATCH / GEMM_BH), 256>>>(
        x, W_in, b_in, gamma_ptr, HID, HID, 0);

    // 2) fused scores + online softmax + partial c_t (single context pass)
    attn_pass_kernel<<<dim3(NSPLIT, BATCH), 256, ATTN_SMEM>>>(ctx);

    // 3) cross-split reduce + cat build + weights (parallel)
    reduce_c_kernel<<<dim3(BATCH, 5), 256>>>(x, topic, outw);

    // 4) output = tanh(cat @ W_out^T + b_out)
    small_gemm_kernel<<<dim3(HID / 32, BATCH / GEMM_BH), 256>>>(
        cat_ptr, W_out, b_out, out, CATK, HID, 1);
}

// round 14
// speedup vs baseline: 1.8434x; 1.0121x over previous
#include <cuda_runtime.h>
#include <cuda_bf16.h>
#include <float.h>
#include <cstdint>

// Problem shape (fixed per reference)
#define BATCH 32
#define SEQ   4096
#define HID   1024
#define TOP   512
#define CATK  (2*HID + TOP)   // 2560

#define NSPLIT 16                        // S-splits per batch in attention pass
#define ROWS_PER_SPLIT (SEQ / NSPLIT)    // 256 rows per CTA
#define WARPS 8
#define ROWS_PER_WARP (ROWS_PER_SPLIT / WARPS)  // 32 rows per warp
#define VPL 8                            // float4 per lane per row (1024/4/32)
#define ATTN_SMEM (WARPS * 2 * 256 * 16) // 64 KB: per-warp double row buffer

#define GEMM_BH 4                        // batches per GEMM CTA (8 slices)
#define GEMM_HW 4                        // h-rows per warp
#define GEMM_TILE_B (GEMM_BH * 64 * 16)  // bytes per tile buffer (4 KB)
#define GEMM_YB (BATCH / GEMM_BH)        // 8 gemm y-slices

// ---------------- scratch (__device__ globals; no allocations) --------------
__device__ float g_gamma [BATCH * HID];
__device__ float g_scores[BATCH * SEQ];
__device__ float g_cpart [BATCH * NSPLIT * HID];
__device__ float g_mzpart[BATCH * NSPLIT * 2];
__device__ float g_cat   [BATCH * CATK];

__device__ __forceinline__ float dot4(float4 a, float4 b)
{
    return a.x * b.x + a.y * b.y + a.z * b.z + a.w * b.w;
}

// recompute global (m, 1/Z) for batch b from the tiny per-split table
__device__ __forceinline__ void softmax_mz(int b, float& mg, float& inv)
{
    mg = -FLT_MAX;
    #pragma unroll
    for (int i = 0; i < NSPLIT; ++i)
        mg = fmaxf(mg, g_mzpart[(b * NSPLIT + i) * 2 + 0]);
    float Zg = 0.f;
    #pragma unroll
    for (int i = 0; i < NSPLIT; ++i) {
        float mi = g_mzpart[(b * NSPLIT + i) * 2 + 0];
        float zi = g_mzpart[(b * NSPLIT + i) * 2 + 1];
        Zg += zi * __expf(mi - mg);
    }
    inv = 1.f / Zg;
}

// ---------------------------------------------------------------------------
// Kernel 1: small GEMM  out[b][h] = act( bias[h] + sum_k in[b][k]*W[h][k] )
// grid = (Hout/32, GEMM_YB + wq), block = 256.
//   y <  GEMM_YB : GEMM slice — warp owns 4 h rows, CTA one 4-batch slice.
//                  Ring-4 cp.async tile buffers, ONE barrier per chunk.
//   y >= GEMM_YB : softmax-weights CTA (gemm2 only): batch = blockIdx.x,
//                  quarter = y - GEMM_YB. Overlaps GEMM compute.
// K: multiple of 256, >= 512. Hout/32 must equal BATCH for weights path.
// ---------------------------------------------------------------------------
__device__ __forceinline__ void stage_tile(uint32_t dst, const float* __restrict__ in,
                                           int b0, int K, int k0, int t)
{
    // 256 float4 total (4 KB), one per thread
    int bb = t >> 6;
    int kk = t & 63;
    const float4* src = (const float4*)(in + (size_t)(b0 + bb) * K + k0) + kk;
    asm volatile("cp.async.cg.shared.global [%0], [%1], 16;\n"
                 :: "r"(dst + t * 16), "l"(src));
}

__global__ void __launch_bounds__(256)
small_gemm_kernel(const float* __restrict__ in, const float* __restrict__ W,
                  const float* __restrict__ bias, float* __restrict__ out,
                  int K, int Hout, int act, float* __restrict__ out_w)
{
    const int t = threadIdx.x;

    // ---- overlapped softmax-weights path (gemm2 launch only) ----
    if (blockIdx.y >= GEMM_YB) {
        const int b = blockIdx.x;                 // 0..31 (= Hout/32 for HID)
        const int q = blockIdx.y - GEMM_YB;       // 0..3
        float mg, inv;
        softmax_mz(b, mg, inv);
        const float4* sc = (const float4*)(g_scores + (size_t)b * SEQ + q * (SEQ / 4));
        float4*       ow = (float4*)(out_w + (size_t)b * SEQ + q * (SEQ / 4));
        float4 s = sc[t];
        float4 w;
        w.x = __expf(s.x - mg) * inv;
        w.y = __expf(s.y - mg) * inv;
        w.z = __expf(s.z - mg) * inv;
        w.w = __expf(s.w - mg) * inv;
        ow[t] = w;
        return;
    }

    // ---- GEMM path ----
    __shared__ float4 tile[4][GEMM_BH * 64];   // ring of 4, 16 KB
    const int warp = t >> 5;
    const int lane = t & 31;
    const int hb   = blockIdx.x * 32 + warp * GEMM_HW;   // first h of this warp
    const int b0   = blockIdx.y * GEMM_BH;
    const int N    = K / 256;                  // chunks (4 or 10)

    const uint32_t tbase = (uint32_t)__cvta_generic_to_shared(tile);

    // prologue: stage chunks 0,1 into buffers 0,1
    stage_tile(tbase,               in, b0, K, 0,   t);
    asm volatile("cp.async.commit_group;\n");
    stage_tile(tbase + GEMM_TILE_B, in, b0, K, 256, t);
    asm volatile("cp.async.commit_group;\n");

    const float4* Wp[GEMM_HW];
    #pragma unroll
    for (int h = 0; h < GEMM_HW; ++h)
        Wp[h] = (const float4*)(W + (size_t)(hb + h) * K);   // 64 float4/chunk

    // current-chunk W registers (chunk 0)
    float4 w[GEMM_HW][2];
    #pragma unroll
    for (int h = 0; h < GEMM_HW; ++h) {
        w[h][0] = Wp[h][lane];
        w[h][1] = Wp[h][32 + lane];
    }

    float acc[GEMM_HW][GEMM_BH];
    #pragma unroll
    for (int h = 0; h < GEMM_HW; ++h)
        #pragma unroll
        for (int b = 0; b < GEMM_BH; ++b) acc[h][b] = 0.f;

    for (int ci = 0; ci < N; ++ci) {
        // prefetch next chunk's W into registers (overlaps FFMA below)
        float4 nw[GEMM_HW][2];
        if (ci + 1 < N) {
            #pragma unroll
            for (int h = 0; h < GEMM_HW; ++h) {
                const float4* p = Wp[h] + (ci + 1) * 64;
                nw[h][0] = p[lane];
                nw[h][1] = p[32 + lane];
            }
        } else {
            #pragma unroll
            for (int h = 0; h < GEMM_HW; ++h)
                nw[h][0] = nw[h][1] = make_float4(0.f, 0.f, 0.f, 0.f);
        }

        asm volatile("cp.async.wait_group 1;\n");
        __syncthreads();                       // tile[ci&3] ready; also
                                               // guarantees prior reads of the
                                               // buffer restaged below are done
        const float4* tl = tile[ci & 3];
        #pragma unroll
        for (int half = 0; half < 2; ++half)
            #pragma unroll
            for (int bb = 0; bb < GEMM_BH; ++bb) {
                float4 xv = tl[bb * 64 + half * 32 + lane];
                #pragma unroll
                for (int h = 0; h < GEMM_HW; ++h)
                    acc[h][bb] += dot4(w[h][half], xv);
            }

        // restage 2 ahead into buffer (ci+2)&3 — distinct from the read buffer
        if (ci + 2 < N)
            stage_tile(tbase + ((ci + 2) & 3) * GEMM_TILE_B, in, b0, K,
                       (ci + 2) * 256, t);
        asm volatile("cp.async.commit_group;\n");   // empty group ok

        #pragma unroll
        for (int h = 0; h < GEMM_HW; ++h) {
            w[h][0] = nw[h][0];
            w[h][1] = nw[h][1];
        }
    }

    #pragma unroll
    for (int off = 16; off; off >>= 1)
        #pragma unroll
        for (int h = 0; h < GEMM_HW; ++h)
            #pragma unroll
            for (int bb = 0; bb < GEMM_BH; ++bb)
                acc[h][bb] += __shfl_xor_sync(0xFFFFFFFFu, acc[h][bb], off);

    // epilogue: lanes 0-15 each write one (h, b): h = lane>>2, b = lane&3
    if (lane < 16) {
        const int hl = lane >> 2;
        const int bl = lane & 3;
        float v = acc[hl][bl] + bias[hb + hl];
        if (act) v = tanhf(v);
        out[(size_t)(b0 + bl) * Hout + hb + hl] = v;
    }
}

// ---------------------------------------------------------------------------
// Kernel 2: warp-autonomous fused scores + online softmax + weighted sum,
// with cp.async double-buffered row staging. grid = (NSPLIT, BATCH), block=256.
// ---------------------------------------------------------------------------
__device__ __forceinline__ void stage_row(uint32_t dst_base, const float4* src)
{
    #pragma unroll
    for (int i = 0; i < VPL; ++i)
        asm volatile("cp.async.cg.shared.global [%0], [%1], 16;\n"
                     :: "r"(dst_base + i * 512), "l"(src + i * 32));
}

__global__ void __launch_bounds__(256, 2)
attn_pass_kernel(const float* __restrict__ ctx)
{
    extern __shared__ float4 sbuf[];          // [WARPS][2][256] float4
    __shared__ float s_m[WARPS], s_Z[WARPS];

    const int t     = threadIdx.x;
    const int warp  = t >> 5;
    const int lane  = t & 31;
    const int split = blockIdx.x;
    const int b     = blockIdx.y;

    float4 g[VPL];
    {
        const float4* gp = (const float4*)(g_gamma + (size_t)b * HID);
        #pragma unroll
        for (int i = 0; i < VPL; ++i) g[i] = gp[lane + 32 * i];
    }

    const int row0 = split * ROWS_PER_SPLIT + warp * ROWS_PER_WARP;
    const float4* base = (const float4*)(ctx + ((size_t)b * SEQ + row0) * HID);

    float4* wbuf = sbuf + warp * 2 * 256;
    const uint32_t wbuf_addr =
        (uint32_t)__cvta_generic_to_shared(wbuf) + (uint32_t)lane * 16;

    #pragma unroll
    for (int pre = 0; pre < 2; ++pre) {
        stage_row(wbuf_addr + pre * 4096, base + pre * 256 + lane);
        asm volatile("cp.async.commit_group;\n");
    }

    float  m = -FLT_MAX, Z = 0.f;
    float4 c[VPL];
    #pragma unroll
    for (int i = 0; i < VPL; ++i) c[i] = make_float4(0.f, 0.f, 0.f, 0.f);

    for (int r = 0; r < ROWS_PER_WARP; ++r) {
        asm volatile("cp.async.wait_group 1;\n");
        __syncwarp();

        const float4* vbuf = wbuf + (r & 1) * 256;
        float4 v[VPL];
        #pragma unroll
        for (int i = 0; i < VPL; ++i) v[i] = vbuf[lane + 32 * i];
        __syncwarp();

        if (r + 2 < ROWS_PER_WARP)
            stage_row(wbuf_addr + (r & 1) * 4096, base + (r + 2) * 256 + lane);
        asm volatile("cp.async.commit_group;\n");

        float p = 0.f;
        #pragma unroll
        for (int i = 0; i < VPL; ++i)
            p += v[i].x * g[i].x + v[i].y * g[i].y + v[i].z * g[i].z + v[i].w * g[i].w;

        #pragma unroll
        for (int off = 16; off; off >>= 1)
            p += __shfl_xor_sync(0xFFFFFFFFu, p, off);

        if (lane == 0) g_scores[(size_t)b * SEQ + row0 + r] = p;

        if (p > m) {
            const float scale = __expf(m - p);
            Z *= scale;
            #pragma unroll
            for (int i = 0; i < VPL; ++i) {
                c[i].x *= scale; c[i].y *= scale;
                c[i].z *= scale; c[i].w *= scale;
            }
            m = p;
        }
        const float e = __expf(p - m);
        Z += e;
        #pragma unroll
        for (int i = 0; i < VPL; ++i) {
            c[i].x += e * v[i].x;  c[i].y += e * v[i].y;
            c[i].z += e * v[i].z;  c[i].w += e * v[i].w;
        }
    }

    asm volatile("cp.async.wait_group 0;\n");
    __syncthreads();
    float* s_c = (float*)sbuf;
    #pragma unroll
    for (int i = 0; i < VPL; ++i)
        ((float4*)(s_c + warp * HID))[lane + 32 * i] = c[i];
    if (lane == 0) { s_m[warp] = m; s_Z[warp] = Z; }
    __syncthreads();

    float mg = s_m[0];
    #pragma unroll
    for (int w = 1; w < WARPS; ++w) mg = fmaxf(mg, s_m[w]);

    float wsc[WARPS], Zg = 0.f;
    #pragma unroll
    for (int w = 0; w < WARPS; ++w) {
        wsc[w] = __expf(s_m[w] - mg);
        Zg += s_Z[w] * wsc[w];
    }

    float4 acc = make_float4(0.f, 0.f, 0.f, 0.f);
    #pragma unroll
    for (int w = 0; w < WARPS; ++w) {
        float4 cw = ((const float4*)(s_c + w * HID))[t];
        acc.x += wsc[w] * cw.x;  acc.y += wsc[w] * cw.y;
        acc.z += wsc[w] * cw.z;  acc.w += wsc[w] * cw.w;
    }
    ((float4*)(g_cpart + ((size_t)b * NSPLIT + split) * HID))[t] = acc;
    if (t == 0) {
        g_mzpart[(b * NSPLIT + split) * 2 + 0] = mg;
        g_mzpart[(b * NSPLIT + split) * 2 + 1] = Zg;
    }
}

// ---------------------------------------------------------------------------
// Kernel 3: cross-split reduction -> c_t; builds cat = [c_t | x | topic].
// grid = BATCH, block = 256. (Weights write moved into gemm2 launch.)
// ---------------------------------------------------------------------------
__global__ void __launch_bounds__(256)
reduce_c_kernel(const float* __restrict__ x, const float* __restrict__ topic)
{
    const int b = blockIdx.x;
    const int t = threadIdx.x;

    float mg, inv;
    softmax_mz(b, mg, inv);

    float wsc[NSPLIT];
    #pragma unroll
    for (int i = 0; i < NSPLIT; ++i)
        wsc[i] = __expf(g_mzpart[(b * NSPLIT + i) * 2 + 0] - mg);

    float4 c = make_float4(0.f, 0.f, 0.f, 0.f);
    #pragma unroll
    for (int i = 0; i < NSPLIT; ++i) {
        float4 cp = ((const float4*)(g_cpart + ((size_t)b * NSPLIT + i) * HID))[t];
        c.x += wsc[i] * cp.x;  c.y += wsc[i] * cp.y;
        c.z += wsc[i] * cp.z;  c.w += wsc[i] * cp.w;
    }
    c.x *= inv; c.y *= inv; c.z *= inv; c.w *= inv;

    ((float4*)(g_cat + (size_t)b * CATK))[t] = c;
    ((float4*)(g_cat + (size_t)b * CATK + HID))[t] =
        ((const float4*)(x + (size_t)b * HID))[t];
    if (t < TOP / 4)
        ((float4*)(g_cat + (size_t)b * CATK + 2 * HID))[t] =
            ((const float4*)(topic + (size_t)b * TOP))[t];
}

// ---------------------------------------------------------------------------
extern "C" void kernel_launch(void* const* d_in, const int* in_sizes, int n_in,
                              void* d_out, int out_size)
{
    const float* x     = (const float*)d_in[0];
    const float* ctx   = (const float*)d_in[1];
    const float* topic = (const float*)d_in[2];
    const float* W_in  = (const float*)d_in[3];
    const float* b_in  = (const float*)d_in[4];
    const float* W_out = (const float*)d_in[5];
    const float* b_out = (const float*)d_in[6];

    float* out  = (float*)d_out;                 // [BATCH,HID] output
    float* outw = out + BATCH * HID;             // [BATCH,SEQ] weights

    float* gamma_ptr;
    cudaGetSymbolAddress((void**)&gamma_ptr, g_gamma);
    float* cat_ptr;
    cudaGetSymbolAddress((void**)&cat_ptr, g_cat);

    static int smem_set = 0;
    if (!smem_set) {
        cudaFuncSetAttribute(attn_pass_kernel,
                             cudaFuncAttributeMaxDynamicSharedMemorySize,
                             ATTN_SMEM);
        smem_set = 1;
    }

    // 1) gamma = x @ W_in^T + b_in   (no weights CTAs)
    small_gemm_kernel<<<dim3(HID / 32, GEMM_YB), 256>>>(
        x, W_in, b_in, gamma_ptr, HID, HID, 0, nullptr);

    // 2) fused scores + online softmax + partial c_t (single context pass)
    attn_pass_kernel<<<dim3(NSPLIT, BATCH), 256, ATTN_SMEM>>>(ctx);

    // 3) cross-split reduce + cat build
    reduce_c_kernel<<<BATCH, 256>>>(x, topic);

    // 4) output = tanh(cat @ W_out^T + b_out), with 128 overlapped
    //    softmax-weights CTAs (grid.y 8..11)
    small_gemm_kernel<<<dim3(HID / 32, GEMM_YB + 4), 256>>>(
        cat_ptr, W_out, b_out, out, CATK, HID, 1, outw);
}